// round 1
// baseline (speedup 1.0000x reference)
#include <cuda_runtime.h>

#define BB 8
#define NN 256
#define DD 256
#define HH 128
#define RR 8

// Scratch (allocation-free rule: __device__ globals)
__device__ float g_pi[BB * NN * HH];   // proj_i
__device__ float g_pj[BB * NN * HH];   // proj_j + b1

typedef unsigned long long u64;
union F2U { float2 f; u64 u; };

__device__ __forceinline__ u64 f2add_u(u64 a, u64 b) {
    u64 d;
    asm("add.rn.f32x2 %0, %1, %2;" : "=l"(d) : "l"(a), "l"(b));
    return d;
}
__device__ __forceinline__ u64 f2fma_u(u64 a, u64 b, u64 c) {
    u64 d;
    asm("fma.rn.f32x2 %0, %1, %2, %3;" : "=l"(d) : "l"(a), "l"(b), "l"(c));
    return d;
}
__device__ __forceinline__ u64 fdup(float x) {
    u64 d;
    asm("mov.b64 %0, {%1, %1};" : "=l"(d) : "f"(x));
    return d;
}

// -------------------------------------------------------------------------
// Phase A: proj_i = slots @ W1[:D], proj_j = slots @ W1[D:] + b1
// Grid: 128 blocks x 256 threads. Block = 16 rows of the [2048,256] input.
// Thread t: column h = t&127 of (t<128 ? proj_i : proj_j), all 16 rows,
// accumulated as 8 f32x2 (row pairs).
// -------------------------------------------------------------------------
__global__ __launch_bounds__(256) void proj_kernel(
    const float* __restrict__ slots,
    const float* __restrict__ W1,
    const float* __restrict__ b1)
{
    __shared__ float a_s[256 * 18];   // [k][row], 16 rows padded to 18

    const int t = threadIdx.x;
    const int row0 = blockIdx.x * 16;

    #pragma unroll
    for (int ii = 0; ii < 16; ii++) {
        int idx = t + ii * 256;
        int rr = idx >> 8;          // 0..15
        int k  = idx & 255;         // 0..255
        a_s[k * 18 + rr] = slots[(row0 + rr) * DD + k];
    }
    __syncthreads();

    const int h    = t & 127;
    const int ispj = t >> 7;
    const float* wp = W1 + ispj * (DD * HH) + h;   // W1[k][h], row stride HH

    u64 acc[8];
    #pragma unroll
    for (int r = 0; r < 8; r++) acc[r] = 0ull;

    #pragma unroll 4
    for (int k = 0; k < 256; k++) {
        float w = __ldg(wp + k * HH);
        u64 wd = fdup(w);
        #pragma unroll
        for (int r = 0; r < 8; r++) {
            u64 a2 = *(const u64*)(a_s + k * 18 + 2 * r);
            acc[r] = f2fma_u(a2, wd, acc[r]);
        }
    }

    float bias = ispj ? b1[h] : 0.0f;
    float* dst = ispj ? g_pj : g_pi;
    #pragma unroll
    for (int r = 0; r < 8; r++) {
        F2U cv; cv.u = acc[r];
        int row = row0 + 2 * r;
        dst[row * HH + h]       = cv.f.x + bias;
        dst[(row + 1) * HH + h] = cv.f.y + bias;
    }
}

// -------------------------------------------------------------------------
// Phase B: out[b,i,j,r] = sigmoid( sum_k relu(pi[b,i,k]+pj[b,j,k]) * W2[k,r] + b2[r] )
// Grid (jt, it, b) = (8, 8, 8); block 256 threads covers a 32x32 pair tile;
// each thread: 2i x 2j = 4 pairs (i = ty, ty+16; j = tx, tx+16).
// f32x2 packing over k: acc lanes hold even/odd-k partial sums.
// relu trick: 2*relu(x) = x + |x| (exact), with 0.5*W2 pre-stored (exact).
// -------------------------------------------------------------------------
__global__ __launch_bounds__(256, 2) void pair_kernel(
    const float* __restrict__ W2,
    const float* __restrict__ b2v,
    float* __restrict__ out)
{
    __shared__ float pi_s[32 * 130];  // [i][k], pad 130 for conflict-free LDS.64
    __shared__ float pj_s[32 * 130];  // [j][k]
    __shared__ u64   w2p[64 * 8];     // [k/2][r] = {0.5*W2[k][r], 0.5*W2[k+1][r]}

    const int t  = threadIdx.x;
    const int jt = blockIdx.x, it = blockIdx.y, b = blockIdx.z;
    const int ibase = b * NN + it * 32;
    const int jbase = b * NN + jt * 32;

    #pragma unroll
    for (int ii = 0; ii < 16; ii++) {
        int idx = t + ii * 256;
        int r = idx >> 7;          // 0..31
        int k = idx & 127;
        pi_s[r * 130 + k] = g_pi[(ibase + r) * HH + k];
        pj_s[r * 130 + k] = g_pj[(jbase + r) * HH + k];
    }
    #pragma unroll
    for (int ii = 0; ii < 2; ii++) {
        int idx = t + ii * 256;     // 0..511
        int k2 = idx >> 3, r = idx & 7;
        F2U cv;
        cv.f = make_float2(0.5f * W2[(2 * k2) * RR + r],
                           0.5f * W2[(2 * k2 + 1) * RR + r]);
        w2p[idx] = cv.u;
    }
    __syncthreads();

    const int tx = t & 15, ty = t >> 4;
    const float* pA = pi_s + ty * 130;
    const float* pB = pi_s + (ty + 16) * 130;
    const float* pC = pj_s + tx * 130;
    const float* pD = pj_s + (tx + 16) * 130;

    u64 acc[4][8];
    #pragma unroll
    for (int p = 0; p < 4; p++)
        #pragma unroll
        for (int r = 0; r < 8; r++) acc[p][r] = 0ull;

    const u64 ABSM = 0x7FFFFFFF7FFFFFFFULL;

    #pragma unroll 4
    for (int k = 0; k < 128; k += 2) {
        u64 piA = *(const u64*)(pA + k);
        u64 piB = *(const u64*)(pB + k);
        u64 pjA = *(const u64*)(pC + k);
        u64 pjB = *(const u64*)(pD + k);

        u64 s00 = f2add_u(piA, pjA);
        u64 s01 = f2add_u(piA, pjB);
        u64 s10 = f2add_u(piB, pjA);
        u64 s11 = f2add_u(piB, pjB);

        // 2*relu(x) = x + |x|  (bit-exact; compensated by 0.5*W2)
        u64 h00 = f2add_u(s00, s00 & ABSM);
        u64 h01 = f2add_u(s01, s01 & ABSM);
        u64 h10 = f2add_u(s10, s10 & ABSM);
        u64 h11 = f2add_u(s11, s11 & ABSM);

        const u64* wrow = w2p + (k >> 1) * 8;
        #pragma unroll
        for (int r = 0; r < 8; r++) {
            u64 w = wrow[r];
            acc[0][r] = f2fma_u(h00, w, acc[0][r]);
            acc[1][r] = f2fma_u(h01, w, acc[1][r]);
            acc[2][r] = f2fma_u(h10, w, acc[2][r]);
            acc[3][r] = f2fma_u(h11, w, acc[3][r]);
        }
    }

    float bb[8];
    #pragma unroll
    for (int r = 0; r < 8; r++) bb[r] = b2v[r];

    #pragma unroll
    for (int p = 0; p < 4; p++) {
        int gi = it * 32 + ty + ((p >> 1) << 4);
        int gj = jt * 32 + tx + ((p & 1) << 4);
        float* op = out + (((size_t)(b * NN + gi) * NN + gj) << 3);

        float o[8];
        #pragma unroll
        for (int r = 0; r < 8; r++) {
            F2U cv; cv.u = acc[p][r];
            float s = cv.f.x + cv.f.y + bb[r];
            o[r] = __fdividef(1.0f, 1.0f + __expf(-s));
        }
        *(float4*)op       = make_float4(o[0], o[1], o[2], o[3]);
        *(float4*)(op + 4) = make_float4(o[4], o[5], o[6], o[7]);
    }
}

extern "C" void kernel_launch(void* const* d_in, const int* in_sizes, int n_in,
                              void* d_out, int out_size)
{
    const float* slots = (const float*)d_in[0];
    const float* W1    = (const float*)d_in[1];
    const float* b1    = (const float*)d_in[2];
    const float* W2    = (const float*)d_in[3];
    const float* b2    = (const float*)d_in[4];
    float* out = (float*)d_out;

    proj_kernel<<<128, 256>>>(slots, W1, b1);

    dim3 grid(8, 8, 8);   // (jt, it, b)
    pair_kernel<<<grid, 256>>>(W2, b2, out);
}